// round 12
// baseline (speedup 1.0000x reference)
#include <cuda_runtime.h>
#include <cuda_fp16.h>
#include <cstdint>

#define CZ      128
#define NROWS   (512*512)
#define NTILES  2048
#define THREADS 256
#define GRID    304
#define HGRID   152

#define ZROWB   256                 /* bytes per 128-half row */
#define ZTILE_B (128*ZROWB)         /* 32768 */
#define WHALF_B (64*ZROWB)          /* 16384: 64 n-rows of one weight matrix */

/* smem layout (bytes): z tile + 5 half-weight tiles = 114688 -> 2 CTAs/SM */
#define SM_Z    0
#define SM_W(i) (ZTILE_B + (i) * WHALF_B)
#define SMEM_TOTAL (ZTILE_B + 5 * WHALF_B)

/* fp16 weight scratch, pre-converted + pre-SWIZZLED by prep kernel */
__device__ __align__(16) __half g_wh[5 * 128 * 128];

/* swizzle: 16B chunk index ^= (row & 7). row stride 256B. */
__global__ void cvt_weights(const float* __restrict__ w0, const float* __restrict__ w1,
                            const float* __restrict__ w2, const float* __restrict__ w3,
                            const float* __restrict__ w4) {
    int i = blockIdx.x * blockDim.x + threadIdx.x;   /* 0 .. 81919 */
    int m = i >> 14, idx = i & 16383;
    const float* w = (m == 0) ? w0 : (m == 1) ? w1 : (m == 2) ? w2 : (m == 3) ? w3 : w4;
    int r = idx >> 7, c = idx & 127;
    int pos = r * 128 + ((((c >> 3) ^ (r & 7)) << 3) | (c & 7));
    g_wh[m * 16384 + pos] = __float2half_rn(w[idx]);
}

__device__ __forceinline__ uint32_t smem_u32(const void* p) {
    uint32_t a;
    asm("{ .reg .u64 t; cvta.to.shared.u64 t, %1; cvt.u32.u64 %0, t; }" : "=r"(a) : "l"(p));
    return a;
}

__device__ __forceinline__ void cp16(uint32_t s, uint64_t g) {
    asm volatile("cp.async.cg.shared.global [%0], [%1], 16;" :: "r"(s), "l"(g) : "memory");
}
#define CP_COMMIT() asm volatile("cp.async.commit_group;" ::: "memory")
#define CP_WAIT0()  asm volatile("cp.async.wait_group 0;" ::: "memory")

__device__ __forceinline__ void ldm_x4(uint32_t (&d)[4], uint32_t a) {
    asm volatile("ldmatrix.sync.aligned.m8n8.x4.shared.b16 {%0,%1,%2,%3}, [%4];"
                 : "=r"(d[0]), "=r"(d[1]), "=r"(d[2]), "=r"(d[3]) : "r"(a));
}
__device__ __forceinline__ void mma16816(float (&c)[4], const uint32_t (&a)[4],
                                         uint32_t b0, uint32_t b1) {
    asm volatile("mma.sync.aligned.m16n8k16.row.col.f32.f16.f16.f32 "
                 "{%0,%1,%2,%3}, {%4,%5,%6,%7}, {%8,%9}, {%0,%1,%2,%3};"
                 : "+f"(c[0]), "+f"(c[1]), "+f"(c[2]), "+f"(c[3])
                 : "r"(a[0]), "r"(a[1]), "r"(a[2]), "r"(a[3]), "r"(b0), "r"(b1));
}

/* paired gemm, warp tile m32 x n32: two weight matrices share the A fragments.
   PAIR=false -> single matrix (stage g). */
template <bool PAIR>
__device__ __forceinline__ void gemm_tile(uint32_t zb, uint32_t wp, uint32_t wg,
                                          float (&accP)[2][4][4], float (&accG)[2][4][4],
                                          int lane, int m0, int nl) {
#pragma unroll
    for (int mt = 0; mt < 2; mt++)
#pragma unroll
        for (int nt = 0; nt < 4; nt++)
#pragma unroll
            for (int r = 0; r < 4; r++) { accP[mt][nt][r] = 0.f; if (PAIR) accG[mt][nt][r] = 0.f; }

    const uint32_t r  = (uint32_t)(lane & 15);
    const uint32_t s  = (uint32_t)(lane >> 4);
    const uint32_t x7 = (uint32_t)(lane & 7);
    const uint32_t za0 = zb + (uint32_t)(m0 + r) * ZROWB;
    const uint32_t za1 = za0 + 16 * ZROWB;
    const uint32_t wp0 = wp + (uint32_t)(nl + r) * ZROWB;
    const uint32_t wp1 = wp0 + 16 * ZROWB;
    const uint32_t wg0 = wg + (uint32_t)(nl + r) * ZROWB;
    const uint32_t wg1 = wg0 + 16 * ZROWB;

#pragma unroll
    for (int kt = 0; kt < 8; kt++) {
        const uint32_t off = (((uint32_t)(2 * kt) + s) ^ x7) << 4;
        uint32_t a0[4], a1[4], b0[4], b1[4];
        ldm_x4(a0, za0 + off);
        ldm_x4(a1, za1 + off);
        ldm_x4(b0, wp0 + off);
        ldm_x4(b1, wp1 + off);
        mma16816(accP[0][0], a0, b0[0], b0[2]); mma16816(accP[0][1], a0, b0[1], b0[3]);
        mma16816(accP[0][2], a0, b1[0], b1[2]); mma16816(accP[0][3], a0, b1[1], b1[3]);
        mma16816(accP[1][0], a1, b0[0], b0[2]); mma16816(accP[1][1], a1, b0[1], b0[3]);
        mma16816(accP[1][2], a1, b1[0], b1[2]); mma16816(accP[1][3], a1, b1[1], b1[3]);
        if (PAIR) {
            ldm_x4(b0, wg0 + off);
            ldm_x4(b1, wg1 + off);
            mma16816(accG[0][0], a0, b0[0], b0[2]); mma16816(accG[0][1], a0, b0[1], b0[3]);
            mma16816(accG[0][2], a0, b1[0], b1[2]); mma16816(accG[0][3], a0, b1[1], b1[3]);
            mma16816(accG[1][0], a1, b0[0], b0[2]); mma16816(accG[1][1], a1, b0[1], b0[3]);
            mma16816(accG[1][2], a1, b1[0], b1[2]); mma16816(accG[1][3], a1, b1[1], b1[3]);
        }
    }
}

/* cheap sigmoid for gated outputs: 1 MUFU (tanh) instead of 2 (ex2 + rcp) */
__device__ __forceinline__ float sigm_t(float v) {
    float t;
    asm("tanh.approx.f32 %0, %1;" : "=f"(t) : "f"(v * 0.5f));
    return fmaf(0.5f, t, 0.5f);
}
__device__ __forceinline__ float sigmf(float v) { return 1.0f / (1.0f + __expf(-v)); }

/* epilogue, m32 x n32 warp tile: out = mask * sigmoid(G + gb) * (P + pb).
   cb = global column base of this warp's n tile. biases via __ldg (L1-cached). */
__device__ __forceinline__ void epi_pair(const float (&p)[2][4][4], const float (&g)[2][4][4],
                                         float* __restrict__ ob, long row0,
                                         const float* __restrict__ maskg,
                                         const float* __restrict__ pb,
                                         const float* __restrict__ gbv,
                                         int m0, int cb, int lane) {
    const int tig = lane & 3, grp = lane >> 2;
    const int r0 = m0 + grp;
    const float mk[4] = { __ldg(maskg + row0 + r0),      __ldg(maskg + row0 + r0 + 8),
                          __ldg(maskg + row0 + r0 + 16), __ldg(maskg + row0 + r0 + 24) };
    float* const rp[4] = { ob + (row0 + r0) * CZ,      ob + (row0 + r0 + 8) * CZ,
                           ob + (row0 + r0 + 16) * CZ, ob + (row0 + r0 + 24) * CZ };
#pragma unroll
    for (int nt = 0; nt < 4; nt++) {
        const int c = cb + nt * 8 + tig * 2;
        const float b0 = __ldg(pb + c),  b1 = __ldg(pb + c + 1);
        const float g0 = __ldg(gbv + c), g1 = __ldg(gbv + c + 1);
#pragma unroll
        for (int mt = 0; mt < 2; mt++) {
            float2 v0, v1;
            v0.x = mk[2*mt]   * sigm_t(g[mt][nt][0] + g0) * (p[mt][nt][0] + b0);
            v0.y = mk[2*mt]   * sigm_t(g[mt][nt][1] + g1) * (p[mt][nt][1] + b1);
            v1.x = mk[2*mt+1] * sigm_t(g[mt][nt][2] + g0) * (p[mt][nt][2] + b0);
            v1.y = mk[2*mt+1] * sigm_t(g[mt][nt][3] + g1) * (p[mt][nt][3] + b1);
            *(float2*)(rp[2*mt]   + c) = v0;
            *(float2*)(rp[2*mt+1] + c) = v1;
        }
    }
}

__device__ __forceinline__ void epi_g(const float (&d)[2][4][4], float* __restrict__ ob,
                                      long row0, const float* __restrict__ gbv,
                                      int m0, int cb, int lane) {
    const int tig = lane & 3, grp = lane >> 2;
    const int r0 = m0 + grp;
    float* const rp[4] = { ob + (row0 + r0) * CZ,      ob + (row0 + r0 + 8) * CZ,
                           ob + (row0 + r0 + 16) * CZ, ob + (row0 + r0 + 24) * CZ };
#pragma unroll
    for (int nt = 0; nt < 4; nt++) {
        const int c = cb + nt * 8 + tig * 2;
        const float g0 = __ldg(gbv + c), g1 = __ldg(gbv + c + 1);
#pragma unroll
        for (int mt = 0; mt < 2; mt++) {
            float2 v0, v1;
            v0.x = sigmf(d[mt][nt][0] + g0);
            v0.y = sigmf(d[mt][nt][1] + g1);
            v1.x = sigmf(d[mt][nt][2] + g0);
            v1.y = sigmf(d[mt][nt][3] + g1);
            *(float2*)(rp[2*mt]   + c) = v0;
            *(float2*)(rp[2*mt+1] + c) = v1;
        }
    }
}

/* LayerNorm 16 rows of a 128-row tile into swizzled fp16 z buffer (8 warps). */
__device__ __forceinline__ void do_ln(const float* __restrict__ x, long row0, char* zb,
                                      const float4& w4, const float4& b4,
                                      int rbase, int lane) {
    const uint32_t chunk = (uint32_t)(lane >> 1);
    const uint32_t sub   = (uint32_t)(lane & 1) << 3;
#pragma unroll 4
    for (int i = 0; i < 16; i++) {
        int r = rbase + i;
        float4 v = *(const float4*)(x + (row0 + r) * CZ + lane * 4);
        float s  = v.x + v.y + v.z + v.w;
        float ss = v.x * v.x + v.y * v.y + v.z * v.z + v.w * v.w;
#pragma unroll
        for (int o = 16; o; o >>= 1) {
            s  += __shfl_xor_sync(0xFFFFFFFFu, s, o);
            ss += __shfl_xor_sync(0xFFFFFFFFu, ss, o);
        }
        float mu  = s * (1.0f / 128.0f);
        float var = ss * (1.0f / 128.0f) - mu * mu;
        float rs  = rsqrtf(var + 1e-5f);
        __half2 h01 = __floats2half2_rn((v.x - mu) * rs * w4.x + b4.x,
                                        (v.y - mu) * rs * w4.y + b4.y);
        __half2 h23 = __floats2half2_rn((v.z - mu) * rs * w4.z + b4.z,
                                        (v.w - mu) * rs * w4.w + b4.w);
        uint2 u;
        u.x = *(uint32_t*)&h01;
        u.y = *(uint32_t*)&h23;
        uint32_t sw = ((chunk ^ (uint32_t)(r & 7)) << 4) | sub;
        *(uint2*)(zb + (uint32_t)r * ZROWB + sw) = u;
    }
}

__global__ void __launch_bounds__(THREADS, 2)
tri_kernel(const float* __restrict__ x,   const float* __restrict__ mask,
           const float* __restrict__ lnw, const float* __restrict__ lnb,
           const float* __restrict__ apb, const float* __restrict__ agb,
           const float* __restrict__ bpb, const float* __restrict__ bgb,
           const float* __restrict__ gb,  float* __restrict__ out) {
    extern __shared__ char smem[];
    const uint32_t sbase = smem_u32(smem);
    const int tid = threadIdx.x, wid = tid >> 5, lane = tid & 31;
    const int half = blockIdx.x & 1;          /* which 64-col output half */
    const int t0   = blockIdx.x >> 1;         /* starting tile */
    /* 8 warps: 4 m-groups x 2 n-groups; warp tile m32 x n32 */
    const int m0 = (wid >> 1) * 32;
    const int nl = (wid & 1) * 32;            /* n offset inside this CTA's half */
    const int cb = half * 64 + nl;            /* global output column base */

    /* one-time: this half's rows of all 5 weight matrices -> resident smem */
    {
        const char* src = (const char*)g_wh + half * WHALF_B;
#pragma unroll
        for (int s = 0; s < 5; s++)
            for (int i = tid; i < WHALF_B / 16; i += THREADS)
                cp16(sbase + SM_W(s) + i * 16,
                     (uint64_t)__cvta_generic_to_global(src + s * 2 * WHALF_B + i * 16));
        CP_COMMIT();
    }

    const float4 lw4 = *(const float4*)(lnw + lane * 4);
    const float4 lb4 = *(const float4*)(lnb + lane * 4);
    const uint32_t zb = sbase + SM_Z;

    CP_WAIT0();

    float accP[2][4][4], accG[2][4][4];
    for (int t = t0; t < NTILES; t += HGRID) {
        const long row0 = (long)t * 128;

        __syncthreads();                       /* prior tile's z reads done */
        do_ln(x, row0, smem + SM_Z, lw4, lb4, wid * 16, lane);
        __syncthreads();                       /* z ready */

        /* stage a */
        gemm_tile<true>(zb, sbase + SM_W(0), sbase + SM_W(1), accP, accG, lane, m0, nl);
        epi_pair(accP, accG, out, row0, mask, apb, agb, m0, cb, lane);

        /* stage b */
        gemm_tile<true>(zb, sbase + SM_W(2), sbase + SM_W(3), accP, accG, lane, m0, nl);
        epi_pair(accP, accG, out + (long)NROWS * CZ, row0, mask, bpb, bgb, m0, cb, lane);

        /* stage g */
        gemm_tile<false>(zb, sbase + SM_W(4), sbase + SM_W(4), accP, accG, lane, m0, nl);
        epi_g(accP, out + 2L * NROWS * CZ, row0, gb, m0, cb, lane);
    }
}

extern "C" void kernel_launch(void* const* d_in, const int* in_sizes, int n_in,
                              void* d_out, int out_size) {
    const float* x    = (const float*)d_in[0];
    const float* mask = (const float*)d_in[1];
    const float* lnw  = (const float*)d_in[2];
    const float* lnb  = (const float*)d_in[3];
    const float* apw  = (const float*)d_in[4];
    const float* apb  = (const float*)d_in[5];
    const float* agw  = (const float*)d_in[6];
    const float* agb  = (const float*)d_in[7];
    const float* bpw  = (const float*)d_in[8];
    const float* bpb  = (const float*)d_in[9];
    const float* bgw  = (const float*)d_in[10];
    const float* bgb  = (const float*)d_in[11];
    const float* gw   = (const float*)d_in[12];
    const float* gb   = (const float*)d_in[13];
    float* out = (float*)d_out;

    cvt_weights<<<320, 256>>>(apw, agw, bpw, bgw, gw);

    cudaFuncSetAttribute(tri_kernel, cudaFuncAttributeMaxDynamicSharedMemorySize, SMEM_TOTAL);
    tri_kernel<<<GRID, THREADS, SMEM_TOTAL>>>(x, mask, lnw, lnb,
                                              apb, agb, bpb, bgb, gb, out);
}

// round 15
// speedup vs baseline: 1.2295x; 1.2295x over previous
#include <cuda_runtime.h>
#include <cuda_fp16.h>
#include <cstdint>

#define CZ      128
#define NROWS   (512*512)
#define NTILES  2048
#define THREADS 512
#define GRID    152

#define ZROWB   256                 /* bytes per 128-half row */
#define TILE_B  (128*ZROWB)         /* 32768 bytes = one z/weight tile image */

/* smem layout (bytes) */
#define SM_BIAS 0                   /* 640 f32: apb|agb|bpb|bgb|gb (2560 B) */
#define SM_Z0   2560
#define SM_Z1   (SM_Z0 + TILE_B)
#define SM_W(i) (SM_Z1 + TILE_B + (i) * TILE_B)
#define SMEM_TOTAL (SM_W(5))        /* 231936 <= 232448 */

/* fp16 weight scratch, pre-converted + pre-SWIZZLED by prep kernel */
__device__ __align__(16) __half g_wh[5 * 128 * 128];
/* fp16 z staging: per-tile 32KB images, written phase 1, cp.async'd phase 2 */
__device__ __align__(16) __half g_z[(size_t)NROWS * CZ];

/* swizzle: 16B chunk index ^= (row & 7). row stride 256B. */
__global__ void cvt_weights(const float* __restrict__ w0, const float* __restrict__ w1,
                            const float* __restrict__ w2, const float* __restrict__ w3,
                            const float* __restrict__ w4) {
    int i = blockIdx.x * blockDim.x + threadIdx.x;   /* 0 .. 81919 */
    int m = i >> 14, idx = i & 16383;
    const float* w = (m == 0) ? w0 : (m == 1) ? w1 : (m == 2) ? w2 : (m == 3) ? w3 : w4;
    int r = idx >> 7, c = idx & 127;
    int pos = r * 128 + ((((c >> 3) ^ (r & 7)) << 3) | (c & 7));
    g_wh[m * 16384 + pos] = __float2half_rn(w[idx]);
}

__device__ __forceinline__ uint32_t smem_u32(const void* p) {
    uint32_t a;
    asm("{ .reg .u64 t; cvta.to.shared.u64 t, %1; cvt.u32.u64 %0, t; }" : "=r"(a) : "l"(p));
    return a;
}

__device__ __forceinline__ void cp16(uint32_t s, uint64_t g) {
    asm volatile("cp.async.cg.shared.global [%0], [%1], 16;" :: "r"(s), "l"(g) : "memory");
}
#define CP_COMMIT() asm volatile("cp.async.commit_group;" ::: "memory")
#define CP_WAIT(n)  asm volatile("cp.async.wait_group %0;" :: "n"(n) : "memory")

__device__ __forceinline__ void ldm_x4(uint32_t (&d)[4], uint32_t a) {
    asm volatile("ldmatrix.sync.aligned.m8n8.x4.shared.b16 {%0,%1,%2,%3}, [%4];"
                 : "=r"(d[0]), "=r"(d[1]), "=r"(d[2]), "=r"(d[3]) : "r"(a));
}
__device__ __forceinline__ void mma16816(float (&c)[4], const uint32_t (&a)[4],
                                         uint32_t b0, uint32_t b1) {
    asm volatile("mma.sync.aligned.m16n8k16.row.col.f32.f16.f16.f32 "
                 "{%0,%1,%2,%3}, {%4,%5,%6,%7}, {%8,%9}, {%0,%1,%2,%3};"
                 : "+f"(c[0]), "+f"(c[1]), "+f"(c[2]), "+f"(c[3])
                 : "r"(a[0]), "r"(a[1]), "r"(a[2]), "r"(a[3]), "r"(b0), "r"(b1));
}

/* paired gemm, warp tile m32 x n32: two weight matrices share the A fragments. */
template <bool PAIR>
__device__ __forceinline__ void gemm_tile(uint32_t zb, uint32_t wp, uint32_t wg,
                                          float (&accP)[2][4][4], float (&accG)[2][4][4],
                                          int lane, int m0, int n0) {
#pragma unroll
    for (int mt = 0; mt < 2; mt++)
#pragma unroll
        for (int nt = 0; nt < 4; nt++)
#pragma unroll
            for (int r = 0; r < 4; r++) { accP[mt][nt][r] = 0.f; if (PAIR) accG[mt][nt][r] = 0.f; }

    const uint32_t r  = (uint32_t)(lane & 15);
    const uint32_t s  = (uint32_t)(lane >> 4);
    const uint32_t x7 = (uint32_t)(lane & 7);
    const uint32_t za0 = zb + (uint32_t)(m0 + r) * ZROWB;
    const uint32_t za1 = za0 + 16 * ZROWB;
    const uint32_t wp0 = wp + (uint32_t)(n0 + r) * ZROWB;
    const uint32_t wp1 = wp0 + 16 * ZROWB;
    const uint32_t wg0 = wg + (uint32_t)(n0 + r) * ZROWB;
    const uint32_t wg1 = wg0 + 16 * ZROWB;

#pragma unroll
    for (int kt = 0; kt < 8; kt++) {
        const uint32_t off = (((uint32_t)(2 * kt) + s) ^ x7) << 4;
        uint32_t a0[4], a1[4], b0[4], b1[4];
        ldm_x4(a0, za0 + off);
        ldm_x4(a1, za1 + off);
        ldm_x4(b0, wp0 + off);
        ldm_x4(b1, wp1 + off);
        mma16816(accP[0][0], a0, b0[0], b0[2]); mma16816(accP[0][1], a0, b0[1], b0[3]);
        mma16816(accP[0][2], a0, b1[0], b1[2]); mma16816(accP[0][3], a0, b1[1], b1[3]);
        mma16816(accP[1][0], a1, b0[0], b0[2]); mma16816(accP[1][1], a1, b0[1], b0[3]);
        mma16816(accP[1][2], a1, b1[0], b1[2]); mma16816(accP[1][3], a1, b1[1], b1[3]);
        if (PAIR) {
            ldm_x4(b0, wg0 + off);
            ldm_x4(b1, wg1 + off);
            mma16816(accG[0][0], a0, b0[0], b0[2]); mma16816(accG[0][1], a0, b0[1], b0[3]);
            mma16816(accG[0][2], a0, b1[0], b1[2]); mma16816(accG[0][3], a0, b1[1], b1[3]);
            mma16816(accG[1][0], a1, b0[0], b0[2]); mma16816(accG[1][1], a1, b0[1], b0[3]);
            mma16816(accG[1][2], a1, b1[0], b1[2]); mma16816(accG[1][3], a1, b1[1], b1[3]);
        }
    }
}

/* cheap sigmoid for gated outputs: 1 MUFU (tanh) instead of 2 (ex2 + rcp) */
__device__ __forceinline__ float sigm_t(float v) {
    float t;
    asm("tanh.approx.f32 %0, %1;" : "=f"(t) : "f"(v * 0.5f));
    return fmaf(0.5f, t, 0.5f);
}
__device__ __forceinline__ float sigmf(float v) { return 1.0f / (1.0f + __expf(-v)); }

/* epilogue, m32 x n32 warp tile: out = mask * sigmoid(G + gb) * (P + pb) */
__device__ __forceinline__ void epi_pair(const float (&p)[2][4][4], const float (&g)[2][4][4],
                                         float* __restrict__ ob, long row0,
                                         const float* __restrict__ maskg,
                                         const float* __restrict__ pb,
                                         const float* __restrict__ gbv,
                                         int m0, int n0, int lane) {
    const int tig = lane & 3, grp = lane >> 2;
    const int r0 = m0 + grp;
    const float mk[4] = { __ldg(maskg + row0 + r0),      __ldg(maskg + row0 + r0 + 8),
                          __ldg(maskg + row0 + r0 + 16), __ldg(maskg + row0 + r0 + 24) };
    float* const rp[4] = { ob + (row0 + r0) * CZ,      ob + (row0 + r0 + 8) * CZ,
                           ob + (row0 + r0 + 16) * CZ, ob + (row0 + r0 + 24) * CZ };
#pragma unroll
    for (int nt = 0; nt < 4; nt++) {
        const int c = n0 + nt * 8 + tig * 2;
        const float b0 = pb[c], b1 = pb[c + 1], g0 = gbv[c], g1 = gbv[c + 1];
#pragma unroll
        for (int mt = 0; mt < 2; mt++) {
            float2 v0, v1;
            v0.x = mk[2*mt]   * sigm_t(g[mt][nt][0] + g0) * (p[mt][nt][0] + b0);
            v0.y = mk[2*mt]   * sigm_t(g[mt][nt][1] + g1) * (p[mt][nt][1] + b1);
            v1.x = mk[2*mt+1] * sigm_t(g[mt][nt][2] + g0) * (p[mt][nt][2] + b0);
            v1.y = mk[2*mt+1] * sigm_t(g[mt][nt][3] + g1) * (p[mt][nt][3] + b1);
            *(float2*)(rp[2*mt]   + c) = v0;
            *(float2*)(rp[2*mt+1] + c) = v1;
        }
    }
}

__device__ __forceinline__ void epi_g(const float (&d)[2][4][4], float* __restrict__ ob,
                                      long row0, const float* __restrict__ gbv,
                                      int m0, int n0, int lane) {
    const int tig = lane & 3, grp = lane >> 2;
    const int r0 = m0 + grp;
    float* const rp[4] = { ob + (row0 + r0) * CZ,      ob + (row0 + r0 + 8) * CZ,
                           ob + (row0 + r0 + 16) * CZ, ob + (row0 + r0 + 24) * CZ };
#pragma unroll
    for (int nt = 0; nt < 4; nt++) {
        const int c = n0 + nt * 8 + tig * 2;
        const float g0 = gbv[c], g1 = gbv[c + 1];
#pragma unroll
        for (int mt = 0; mt < 2; mt++) {
            float2 v0, v1;
            v0.x = sigmf(d[mt][nt][0] + g0);
            v0.y = sigmf(d[mt][nt][1] + g1);
            v1.x = sigmf(d[mt][nt][2] + g0);
            v1.y = sigmf(d[mt][nt][3] + g1);
            *(float2*)(rp[2*mt]   + c) = v0;
            *(float2*)(rp[2*mt+1] + c) = v1;
        }
    }
}

/* Phase 1: LayerNorm 8 rows of tile t, STG the pre-swizzled fp16 image to g_z. */
__device__ __forceinline__ void ln_store(const float* __restrict__ x, int t,
                                         const float4& w4, const float4& b4,
                                         int rbase, int lane) {
    const long row0 = (long)t * 128;
    char* const ztile = (char*)g_z + (size_t)t * TILE_B;
    const uint32_t chunk = (uint32_t)(lane >> 1);
    const uint32_t sub   = (uint32_t)(lane & 1) << 3;
#pragma unroll 4
    for (int i = 0; i < 8; i++) {
        int r = rbase + i;
        float4 v = *(const float4*)(x + (row0 + r) * CZ + lane * 4);
        float s  = v.x + v.y + v.z + v.w;
        float ss = v.x * v.x + v.y * v.y + v.z * v.z + v.w * v.w;
#pragma unroll
        for (int o = 16; o; o >>= 1) {
            s  += __shfl_xor_sync(0xFFFFFFFFu, s, o);
            ss += __shfl_xor_sync(0xFFFFFFFFu, ss, o);
        }
        float mu  = s * (1.0f / 128.0f);
        float var = ss * (1.0f / 128.0f) - mu * mu;
        float rs  = rsqrtf(var + 1e-5f);
        __half2 h01 = __floats2half2_rn((v.x - mu) * rs * w4.x + b4.x,
                                        (v.y - mu) * rs * w4.y + b4.y);
        __half2 h23 = __floats2half2_rn((v.z - mu) * rs * w4.z + b4.z,
                                        (v.w - mu) * rs * w4.w + b4.w);
        uint2 u;
        u.x = *(uint32_t*)&h01;
        u.y = *(uint32_t*)&h23;
        uint32_t sw = ((chunk ^ (uint32_t)(r & 7)) << 4) | sub;
        *(uint2*)(ztile + (uint32_t)r * ZROWB + sw) = u;
    }
}

/* cp.async one 32KB z tile image into an smem buffer (all 512 threads) */
__device__ __forceinline__ void fetch_z(uint32_t sdst, int t, int tid) {
    const char* src = (const char*)g_z + (size_t)t * TILE_B;
#pragma unroll
    for (int i = tid; i < TILE_B / 16; i += THREADS)
        cp16(sdst + i * 16, (uint64_t)__cvta_generic_to_global(src + i * 16));
}

__global__ void __launch_bounds__(THREADS, 1)
tri_kernel(const float* __restrict__ x,   const float* __restrict__ mask,
           const float* __restrict__ lnw, const float* __restrict__ lnb,
           const float* __restrict__ apb, const float* __restrict__ agb,
           const float* __restrict__ bpb, const float* __restrict__ bgb,
           const float* __restrict__ gb,  float* __restrict__ out) {
    extern __shared__ char smem[];
    const uint32_t sbase = smem_u32(smem);
    const int tid = threadIdx.x, wid = tid >> 5, lane = tid & 31;
    /* 16 warps: 4 m-groups x 4 n-groups; warp tile m32 x n32 */
    const int m0 = (wid >> 2) * 32, n0 = (wid & 3) * 32;
    const int lnrow = m0 + (wid & 3) * 8;

    /* weights -> resident smem (cp.async group, waited via the z-wait chain) */
    {
        const char* src = (const char*)g_wh;
#pragma unroll
        for (int i = tid; i < 5 * TILE_B / 16; i += THREADS)
            cp16(sbase + SM_W(0) + i * 16, (uint64_t)__cvta_generic_to_global(src + i * 16));
        CP_COMMIT();
    }

    /* biases -> smem */
    float* sb = (float*)(smem + SM_BIAS);
    for (int i = tid; i < 640; i += THREADS) {
        int j = i & 127, which = i >> 7;
        sb[i] = (which == 0) ? apb[j] : (which == 1) ? agb[j] :
                (which == 2) ? bpb[j] : (which == 3) ? bgb[j] : gb[j];
    }

    const float4 lw4 = *(const float4*)(lnw + lane * 4);
    const float4 lb4 = *(const float4*)(lnb + lane * 4);

    /* ---- Phase 1: LayerNorm all owned tiles -> g_z (streaming) ---- */
    for (int t = blockIdx.x; t < NTILES; t += GRID)
        ln_store(x, t, lw4, lb4, lnrow, lane);
    __threadfence();       /* z visible device-wide before cp.async reads */
    __syncthreads();       /* all threads' stores (and biases) done */

    /* ---- Phase 2: async-fed GEMM loop ---- */
    const int t0 = blockIdx.x;
    fetch_z(sbase + SM_Z0, t0, tid);
    CP_COMMIT();
    if (t0 + GRID < NTILES) fetch_z(sbase + SM_Z1, t0 + GRID, tid);
    CP_COMMIT();

    float accP[2][4][4], accG[2][4][4];
    int buf = 0;
    for (int t = t0; t < NTILES; t += GRID) {
        const long row0 = (long)t * 128;
        const uint32_t zb = sbase + (buf ? SM_Z1 : SM_Z0);

        CP_WAIT(1);            /* z(t) (and, first time, weights) landed */
        __syncthreads();       /* visible to all warps */

        gemm_tile<true>(zb, sbase + SM_W(0), sbase + SM_W(1), accP, accG, lane, m0, n0);
        epi_pair(accP, accG, out, row0, mask, sb, sb + 128, m0, n0, lane);

        gemm_tile<true>(zb, sbase + SM_W(2), sbase + SM_W(3), accP, accG, lane, m0, n0);
        epi_pair(accP, accG, out + (long)NROWS * CZ, row0, mask,
                 sb + 256, sb + 384, m0, n0, lane);

        gemm_tile<false>(zb, sbase + SM_W(4), sbase + SM_W(4), accP, accG, lane, m0, n0);
        epi_g(accP, out + 2L * NROWS * CZ, row0, sb + 512, m0, n0, lane);

        __syncthreads();       /* all warps done reading buf */
        const int tn2 = t + 2 * GRID;
        if (tn2 < NTILES) fetch_z(zb, tn2, tid);
        CP_COMMIT();           /* commit (possibly empty) keeps group count aligned */
        buf ^= 1;
    }
}

extern "C" void kernel_launch(void* const* d_in, const int* in_sizes, int n_in,
                              void* d_out, int out_size) {
    const float* x    = (const float*)d_in[0];
    const float* mask = (const float*)d_in[1];
    const float* lnw  = (const float*)d_in[2];
    const float* lnb  = (const float*)d_in[3];
    const float* apw  = (const float*)d_in[4];
    const float* apb  = (const float*)d_in[5];
    const float* agw  = (const float*)d_in[6];
    const float* agb  = (const float*)d_in[7];
    const float* bpw  = (const float*)d_in[8];
    const float* bpb  = (const float*)d_in[9];
    const float* bgw  = (const float*)d_in[10];
    const float* bgb  = (const float*)d_in[11];
    const float* gw   = (const float*)d_in[12];
    const float* gb   = (const float*)d_in[13];
    float* out = (float*)d_out;

    cvt_weights<<<320, 256>>>(apw, agw, bpw, bgw, gw);

    cudaFuncSetAttribute(tri_kernel, cudaFuncAttributeMaxDynamicSharedMemorySize, SMEM_TOTAL);
    tri_kernel<<<GRID, THREADS, SMEM_TOTAL>>>(x, mask, lnw, lnb,
                                              apb, agb, bpb, bgb, gb, out);
}